// round 13
// baseline (speedup 1.0000x reference)
#include <cuda_runtime.h>
#include <cstdint>

#define Tt   4096
#define Hh   512
#define H3   1536
#define NCTA 128
#define NTH  384
#define CANARY 0x7FA00BADu

__device__ float g_XW  [Tt * H3];
__device__ float g_XWa [Tt * Hh];
__device__ float g_XwWw[Tt * 4 * H3];
__device__ float g_cw  [2][4 * Hh];
__device__ float g_hbuf3[3][Hh];
__device__ int   g_maskw[Tt * 4];
__device__ unsigned g_flag_cw[NCTA * 64];
__device__ int g_mask_kind;

// ---- mask dtype detection (u8/i32/f32) ----
__global__ void detect_kernel(const unsigned* __restrict__ wm) {
    __shared__ int f_gt1, f_f32;
    if (threadIdx.x == 0) { f_gt1 = 0; f_f32 = 0; }
    __syncthreads();
    for (int i = threadIdx.x; i < 4096; i += blockDim.x) {
        unsigned v = wm[i];
        if (v == 0x3F800000u) atomicOr(&f_f32, 1);
        else if (v > 1u)      atomicOr(&f_gt1, 1);
    }
    __syncthreads();
    if (threadIdx.x == 0) g_mask_kind = f_f32 ? 2 : (f_gt1 ? 0 : 1);
}

// ---- expand masks + arm canaries + zero cw flags ----
__global__ void expand_masks(const void* __restrict__ wm) {
    int i = blockIdx.x * blockDim.x + threadIdx.x;   // 0..16383
    int mk = g_mask_kind;
    int m;
    if (mk == 0)      m = ((const unsigned char*)wm)[i] != 0;
    else if (mk == 2) m = ((const float*)wm)[i] != 0.f;
    else              m = ((const int*)wm)[i] != 0;
    g_maskw[i] = m;
    if (i < 3 * Hh) ((unsigned*)g_hbuf3)[i] = CANARY;
    if (i < NCTA * 64) g_flag_cw[i] = 0u;
}

// ---- merged batched GEMM: 3 segments dispatched on blockIdx.x ----
#define BM 64
#define BN 64
#define BK 8
__global__ void gemm_all_kernel(const float* __restrict__ x, const int* __restrict__ wid,
                                const float* __restrict__ emb,
                                const float* __restrict__ W,  const float* __restrict__ b,
                                const float* __restrict__ Wa, const float* __restrict__ ba,
                                const float* __restrict__ Ww, const float* __restrict__ bw) {
    __shared__ float As[BK][BM];
    __shared__ float Bs[BK][BN];
    int bx = blockIdx.x;
    const float* A; const int* idx = nullptr;
    const float* B; const float* bias; float* C;
    int K, N, nx, rel;
    if (bx < 1536)      { rel = bx;        A = x;   B = W;  bias = b;  C = g_XW;   K = 128; N = 1536; nx = 24; }
    else if (bx < 2048) { rel = bx - 1536; A = x;   B = Wa; bias = ba; C = g_XWa;  K = 128; N = 512;  nx = 8;  }
    else                { rel = bx - 2048; A = emb; B = Ww; bias = bw; C = g_XwWw; K = 256; N = 1536; nx = 24; idx = wid; }
    const int bn0 = (rel % nx) * BN, bm0 = (rel / nx) * BM;
    const int tid = threadIdx.x;
    const int tx = tid & 15, ty = tid >> 4;
    const int lm = tid >> 2, lkk = (tid & 3) * 2;
    int arow = bm0 + lm;
    if (idx) arow = idx[arow];
    const float* aptr = A + (size_t)arow * K;
    const int bn = tid & 63, bkk = tid >> 6;

    float acc[4][4];
#pragma unroll
    for (int i = 0; i < 4; ++i)
#pragma unroll
        for (int j = 0; j < 4; ++j) acc[i][j] = 0.f;

    for (int k0 = 0; k0 < K; k0 += BK) {
        As[lkk][lm]     = aptr[k0 + lkk];
        As[lkk + 1][lm] = aptr[k0 + lkk + 1];
        Bs[bkk][bn]     = B[(size_t)(k0 + bkk) * N + bn0 + bn];
        Bs[bkk + 4][bn] = B[(size_t)(k0 + bkk + 4) * N + bn0 + bn];
        __syncthreads();
#pragma unroll
        for (int kk = 0; kk < BK; ++kk) {
            float4 av = *reinterpret_cast<const float4*>(&As[kk][ty * 4]);
            float4 bv = *reinterpret_cast<const float4*>(&Bs[kk][tx * 4]);
            float a[4] = {av.x, av.y, av.z, av.w};
            float b4[4] = {bv.x, bv.y, bv.z, bv.w};
#pragma unroll
            for (int i = 0; i < 4; ++i)
#pragma unroll
                for (int j = 0; j < 4; ++j) acc[i][j] += a[i] * b4[j];
        }
        __syncthreads();
    }
#pragma unroll
    for (int i = 0; i < 4; ++i) {
        size_t rbase = (size_t)(bm0 + ty * 4 + i) * N + bn0 + tx * 4;
#pragma unroll
        for (int j = 0; j < 4; ++j)
            C[rbase + j] = acc[i][j] + bias[bn0 + tx * 4 + j];
    }
}

// ---- primitives ----
__device__ __forceinline__ void flag_post(unsigned* slot, unsigned epoch) {
    asm volatile("st.release.gpu.u32 [%0], %1;" :: "l"(slot), "r"(epoch) : "memory");
}
__device__ __forceinline__ void flag_wait(const unsigned* slot, unsigned epoch) {
    unsigned v;
    do {
        asm volatile("ld.acquire.gpu.u32 %0, [%1];" : "=r"(v) : "l"(slot) : "memory");
    } while (v < epoch);
}
__device__ __forceinline__ float4 ld_vol4(const float* p) {
    float4 v;
    asm volatile("ld.volatile.global.v4.f32 {%0,%1,%2,%3}, [%4];"
                 : "=f"(v.x), "=f"(v.y), "=f"(v.z), "=f"(v.w) : "l"(p) : "memory");
    return v;
}
__device__ __forceinline__ void st_canary16(float* p) {
    asm volatile("st.global.v4.u32 [%0], {%1,%1,%1,%1};" :: "l"(p), "r"(CANARY) : "memory");
}
#define FENCE_ACQREL() asm volatile("fence.acq_rel.gpu;" ::: "memory")
#define BARW()         asm volatile("bar.sync 1, 256;" ::: "memory")

__device__ __forceinline__ void cp16(uint32_t saddr, const void* g) {
    asm volatile("cp.async.cg.shared.global [%0], [%1], 16;" :: "r"(saddr), "l"(g) : "memory");
}
__device__ __forceinline__ void cp_commit() {
    asm volatile("cp.async.commit_group;" ::: "memory");
}

struct CBuf {           // 288 B, 16B-aligned fields
    float xw[12];       // XW cols   (g*4+jl)
    float xa[4];        // XWa cols
    float xww[48];      // XwWw cols (w*12 + g*4 + jl)
    int   mask[4];
    int   start[4];
};

__device__ __forceinline__ float sigf(float v) { return 1.f / (1.f + expf(-v)); }

#define SMEM_FLOATS 6144
#define SMEM_BYTES  (SMEM_FLOATS * 4)

__global__ void __launch_bounds__(NTH, 1)
lattice_seq_kernel(const float* __restrict__ h0, const float* __restrict__ c0,
                   const int* __restrict__ wstarts,
                   const float* __restrict__ U, const float* __restrict__ Ua,
                   const float* __restrict__ Uw, float* __restrict__ out) {
    extern __shared__ float sm[];
    // runtime layout (floats):
    // 0..1023    sh ping-pong: two 512-float h buffers (float4 view, 128 slices each)
    // 1024..3071 scw (2048)
    float4* scw4   = (float4*)(sm + 1024);
    float*  sg     = sm + 3072;              // 12 gates
    float*  salpha = sm + 3088;              // 16
    float*  rc     = sm + 3104;              // ring: own c slice [6][4]
    float*  rhuw   = sm + 3136;              // ring: own huw cols [6][12]
    float*  swcw   = sm + 3216;              // 16 scratch (late-word gather)
    CBuf*   cbuf   = (CBuf*)(sm + 3232);     // triple buffer

    const int tid = threadIdx.x;
    const int r   = blockIdx.x;
    const int d   = tid >> 3,  l   = tid & 7;
    const int g16 = tid >> 4,  l16 = tid & 15;
    const int ajl = g16 & 3,   aw  = g16 >> 2;

    // ========== init: weights -> registers via coalesced SMEM staging ==========
    float wreg[64];   // U col slice (d<12) or Uw col slice (12<=d<24)
    float ua[32];     // Ua col slice (alpha threads)
    {
        for (int e = tid; e < 3 * 512; e += NTH) {
            int gg = e >> 9, i = e & 511;
            float4 v = *reinterpret_cast<const float4*>(&U[(size_t)i * H3 + gg * 512 + r * 4]);
            sm[(gg * 4 + 0) * 512 + i] = v.x; sm[(gg * 4 + 1) * 512 + i] = v.y;
            sm[(gg * 4 + 2) * 512 + i] = v.z; sm[(gg * 4 + 3) * 512 + i] = v.w;
        }
        __syncthreads();
        if (d < 12) {
            int base = d * 512 + l * 4;
#pragma unroll
            for (int m = 0; m < 16; ++m)
#pragma unroll
                for (int k = 0; k < 4; ++k) wreg[m * 4 + k] = sm[base + m * 32 + k];
        }
        __syncthreads();
        for (int e = tid; e < 3 * 512; e += NTH) {
            int gg = e >> 9, i = e & 511;
            float4 v = *reinterpret_cast<const float4*>(&Uw[(size_t)i * H3 + gg * 512 + r * 4]);
            sm[(gg * 4 + 0) * 512 + i] = v.x; sm[(gg * 4 + 1) * 512 + i] = v.y;
            sm[(gg * 4 + 2) * 512 + i] = v.z; sm[(gg * 4 + 3) * 512 + i] = v.w;
        }
        __syncthreads();
        if (d >= 12 && d < 24) {
            int base = (d - 12) * 512 + l * 4;
#pragma unroll
            for (int m = 0; m < 16; ++m)
#pragma unroll
                for (int k = 0; k < 4; ++k) wreg[m * 4 + k] = sm[base + m * 32 + k];
        }
        __syncthreads();
        for (int e = tid; e < 512; e += NTH) {
            float4 v = *reinterpret_cast<const float4*>(&Ua[(size_t)e * Hh + r * 4]);
            sm[0 * 512 + e] = v.x; sm[1 * 512 + e] = v.y;
            sm[2 * 512 + e] = v.z; sm[3 * 512 + e] = v.w;
        }
        __syncthreads();
        {
            int base = ajl * 512 + l16 * 4;
#pragma unroll
            for (int m = 0; m < 8; ++m)
#pragma unroll
                for (int k = 0; k < 4; ++k) ua[m * 4 + k] = sm[base + m * 64 + k];
        }
        __syncthreads();
    }

    // cp.async prefetch of step t1 constants into cbuf[t1%3] (threads 192..209)
    auto issue_prefetch = [&](int t1) {
        int e = tid - 192;
        if (e >= 0 && e < 18) {
            CBuf* nb2 = cbuf + (t1 % 3);
            const void* src;
            uint32_t dst;
            if (e < 12) {
                int w = e / 3, gg = e % 3;
                src = &g_XwWw[((size_t)(t1 * 4 + w)) * H3 + gg * 512 + r * 4];
                dst = (uint32_t)__cvta_generic_to_shared(&nb2->xww[e * 4]);
            } else if (e < 15) {
                int gg = e - 12;
                src = &g_XW[(size_t)t1 * H3 + gg * 512 + r * 4];
                dst = (uint32_t)__cvta_generic_to_shared(&nb2->xw[gg * 4]);
            } else if (e == 15) {
                src = &g_XWa[(size_t)t1 * Hh + r * 4];
                dst = (uint32_t)__cvta_generic_to_shared(nb2->xa);
            } else if (e == 16) {
                src = &wstarts[t1 * 4];
                dst = (uint32_t)__cvta_generic_to_shared(nb2->start);
            } else {
                src = &g_maskw[t1 * 4];
                dst = (uint32_t)__cvta_generic_to_shared(nb2->mask);
            }
            cp16(dst, src);
            cp_commit();
        }
    };

    // prime: h0 -> sh buffer 0 (pollers), cbuf for steps 0,1
    if (tid >= 256) ((float4*)sm)[tid - 256] = ((const float4*)h0)[tid - 256];
    issue_prefetch(0);
    issue_prefetch(1);
    if (tid >= 192 && tid < 210)
        asm volatile("cp.async.wait_group 0;" ::: "memory");
    __syncthreads();

    unsigned lt = 0;   // late-step epoch (identical across CTAs)

    for (int t = 0; t < Tt; ++t) {
        if (tid >= 256) {
            // ======== background poller: fetch h[t] for next step ========
            int i = tid - 256;
            if (t + 1 < Tt && i != r) {
                const float* p = &g_hbuf3[t % 3][i * 4];
                float4 v;
                do { v = ld_vol4(p); } while (__float_as_uint(v.x) == CANARY);
                FENCE_ACQREL();
                ((float4*)sm)[((t + 1) & 1) * 128 + i] = v;
            }
        } else {
            // ======== worker path (warps 0-7) ========
            CBuf* cb = cbuf + (t % 3);
            CBuf* nb = cbuf + ((t + 1) % 3);
            const int m0 = cb->mask[0], m1 = cb->mask[1], m2 = cb->mask[2], m3 = cb->mask[3];
            const int anyw = m0 | m1 | m2 | m3;
            const int haslate = (m0 & (cb->start[0] == t - 1)) | (m1 & (cb->start[1] == t - 1))
                              | (m2 & (cb->start[2] == t - 1)) | (m3 & (cb->start[3] == t - 1));
            if (haslate) ++lt;

            const float4* shcur = (const float4*)sm + (t & 1) * 128;

            // ---- dot phase (0-191) ∥ prefetch (192-209) ∥ canary (210) ∥ prestage (211-255) ----
            if (tid < 192) {
                float a0 = 0.f, a1 = 0.f, a2 = 0.f, a3 = 0.f;
#pragma unroll
                for (int m = 0; m < 16; ++m) {
                    float4 hv = shcur[m * 8 + l];
                    a0 += wreg[m * 4 + 0] * hv.x;
                    a1 += wreg[m * 4 + 1] * hv.y;
                    a2 += wreg[m * 4 + 2] * hv.z;
                    a3 += wreg[m * 4 + 3] * hv.w;
                }
                float acc = (a0 + a1) + (a2 + a3);
                acc += __shfl_down_sync(0xffffffffu, acc, 4, 8);
                acc += __shfl_down_sync(0xffffffffu, acc, 2, 8);
                acc += __shfl_down_sync(0xffffffffu, acc, 1, 8);
                if (l == 0) {
                    if (d < 12) sg[d] = cb->xw[d] + acc;
                    else if (t > 0) rhuw[((t - 1) % 6) * 12 + (d - 12)] = acc;
                }
            } else if (tid < 210) {
                if (t + 2 < Tt) issue_prefetch(t + 2);
                asm volatile("cp.async.wait_group 1;" ::: "memory");
            } else if (tid == 210) {
                // arm canary for the buffer that will carry h[t+1]
                st_canary16(&g_hbuf3[(t + 1) % 3][r * 4]);
            } else if (anyw && !haslate) {
                const float4* src = (const float4*)g_cw[t & 1];
                for (int e = tid - 211; e < 512; e += 45)
                    scw4[e] = __ldcg(src + e);
            }
            BARW();   // S2

            // ---- word phase ----
            if (haslate && tid < 16) {          // late words (start == t-1)
                int w = tid >> 2, jl = tid & 3;
                float cwv = 0.f;
                if (cb->mask[w] && cb->start[w] == t - 1) {
                    int s = cb->start[w], slot = (s % 6) * 12;
                    float fv = cb->xww[w * 12 + 0 + jl] + rhuw[slot + 0 + jl];
                    float iv = cb->xww[w * 12 + 4 + jl] + rhuw[slot + 4 + jl];
                    float gv = cb->xww[w * 12 + 8 + jl] + rhuw[slot + 8 + jl];
                    float cs = rc[(s % 6) * 4 + jl];
                    cwv = sigf(fv) * cs + sigf(iv) * tanhf(gv);
                }
                swcw[tid] = cwv;
            }
            if (tid >= 16 && tid < 32 && t + 1 < Tt) {   // early words of step t+1
                int w = (tid - 16) >> 2, jl = tid & 3;
                if (nb->mask[w] && nb->start[w] != t) {
                    int s = nb->start[w], slot = (s % 6) * 12;
                    float fv = nb->xww[w * 12 + 0 + jl] + rhuw[slot + 0 + jl];
                    float iv = nb->xww[w * 12 + 4 + jl] + rhuw[slot + 4 + jl];
                    float gv = nb->xww[w * 12 + 8 + jl] + rhuw[slot + 8 + jl];
                    float cs = rc[(s % 6) * 4 + jl];
                    g_cw[(t + 1) & 1][(w << 9) + r * 4 + jl] = sigf(fv) * cs + sigf(iv) * tanhf(gv);
                }
            }
            if (tid >= 128 && tid < 140) {      // gate activations
                int dd = tid - 128;
                float v = sg[dd];
                sg[dd] = (dd >= 8) ? tanhf(v) : sigf(v);
            }
            if (haslate) {
                if (tid < 32) {
                    __syncwarp(0xffffffffu);
                    if (tid < 4) {               // one STG.128 per word slice
                        int w = tid;
                        if (cb->mask[w] && cb->start[w] == t - 1) {
                            float4 cv = *reinterpret_cast<float4*>(&swcw[w * 4]);
                            *reinterpret_cast<float4*>(&g_cw[t & 1][(w << 9) + r * 4]) = cv;
                        }
                    }
                    __syncwarp(0xffffffffu);
                    if (tid == 0) flag_post(&g_flag_cw[r * 64], lt);
                }
                if (tid < 128) {                 // pipelined c_w gather
                    flag_wait(&g_flag_cw[tid * 64], lt);
                    const float4* src = (const float4*)g_cw[t & 1];
#pragma unroll
                    for (int w = 0; w < 4; ++w)
                        scw4[(w << 7) + tid] = __ldcg(src + (w << 7) + tid);
                }
            }
            BARW();   // S3

            if (tid == 0) FENCE_ACQREL();   // release: canary + early-cw ordered before h STG below

            // ---- alpha dots ----
            if (anyw) {
                float a0 = 0.f, a1 = 0.f, a2 = 0.f, a3 = 0.f;
                const float4* cc4 = scw4 + (aw << 7);
#pragma unroll
                for (int m = 0; m < 8; ++m) {
                    float4 cv = cc4[m * 16 + l16];
                    a0 += ua[m * 4 + 0] * cv.x;
                    a1 += ua[m * 4 + 1] * cv.y;
                    a2 += ua[m * 4 + 2] * cv.z;
                    a3 += ua[m * 4 + 3] * cv.w;
                }
                float acc = (a0 + a1) + (a2 + a3);
                acc += __shfl_down_sync(0xffffffffu, acc, 8, 16);
                acc += __shfl_down_sync(0xffffffffu, acc, 4, 16);
                acc += __shfl_down_sync(0xffffffffu, acc, 2, 16);
                acc += __shfl_down_sync(0xffffffffu, acc, 1, 16);
                if (l16 == 0) salpha[g16] = sigf(cb->xa[ajl] + acc);
                BARW();   // S4
            }

            // ---- combine in warp 0; lane 0 publishes immediately ----
            if (tid < 32) {
                float h1 = 0.f, c1 = 0.f;
                if (tid < 4) {
                    int j = r * 4 + tid;
                    float ig = sg[tid], og = sg[4 + tid], gg = sg[8 + tid];
                    if (anyw) {
                        float e0 = expf(ig);
                        float den = e0, num = e0 * gg;
#pragma unroll
                        for (int w = 0; w < 4; ++w)
                            if (cb->mask[w]) {
                                float ew = expf(salpha[(w << 2) + tid]);
                                den += ew;
                                num += ew * ((const float*)scw4)[(w << 9) + j];
                            }
                        c1 = num / den;
                    } else {
                        float cprev = (t == 0) ? c0[j] : rc[((t - 1) % 6) * 4 + tid];
                        c1 = (1.f - ig) * cprev + ig * gg;
                    }
                    h1 = og * tanhf(c1);
                    rc[(t % 6) * 4 + tid] = c1;
                }
                float x0 = __shfl_sync(0xffffffffu, h1, 0);
                float x1 = __shfl_sync(0xffffffffu, h1, 1);
                float x2 = __shfl_sync(0xffffffffu, h1, 2);
                float x3 = __shfl_sync(0xffffffffu, h1, 3);
                if (tid == 0) {
                    float4 hv; hv.x = x0; hv.y = x1; hv.z = x2; hv.w = x3;
                    *reinterpret_cast<float4*>(&g_hbuf3[t % 3][r * 4]) = hv;   // the message
                    ((float4*)sm)[((t + 1) & 1) * 128 + r] = hv;               // own slot locally
                }
                if (tid < 4) {                 // output writes, off critical path
                    out[(size_t)t * 1024 + r * 4 + tid]       = h1;
                    out[(size_t)t * 1024 + 512 + r * 4 + tid] = c1;
                }
            }
        }
        __syncthreads();   // S1 of next step (all 384)
    }
}

extern "C" void kernel_launch(void* const* d_in, const int* in_sizes, int n_in,
                              void* d_out, int out_size) {
    const float* x   = (const float*)d_in[0];
    const int*   wid = (const int*)d_in[1];
    const int*   wst = (const int*)d_in[2];
    const void*  wm  = d_in[3];
    const float* h0  = (const float*)d_in[4];
    const float* c0  = (const float*)d_in[5];
    const float* emb = (const float*)d_in[6];
    const float* W   = (const float*)d_in[7];
    const float* U   = (const float*)d_in[8];
    const float* b   = (const float*)d_in[9];
    const float* Wa  = (const float*)d_in[10];
    const float* Ua  = (const float*)d_in[11];
    const float* ba  = (const float*)d_in[12];
    const float* Ww  = (const float*)d_in[13];
    const float* Uw  = (const float*)d_in[14];
    const float* bw  = (const float*)d_in[15];
    float* out = (float*)d_out;

    cudaFuncSetAttribute(lattice_seq_kernel,
                         cudaFuncAttributeMaxDynamicSharedMemorySize, SMEM_BYTES);

    detect_kernel<<<1, 256>>>((const unsigned*)wm);
    expand_masks<<<64, 256>>>(wm);
    gemm_all_kernel<<<8192, 256>>>(x, wid, emb, W, b, Wa, ba, Ww, bw);
    lattice_seq_kernel<<<NCTA, NTH, SMEM_BYTES>>>(h0, c0, wst, U, Ua, Uw, out);
}

// round 14
// speedup vs baseline: 2.2841x; 2.2841x over previous
#include <cuda_runtime.h>
#include <cstdint>

#define Tt   4096
#define Hh   512
#define H3   1536
#define NCTA 64
#define NTH  384

__device__ float g_XW  [Tt * H3];
__device__ float g_XWa [Tt * Hh];
__device__ float g_XwWw[Tt * 4 * H3];
__device__ float g_cw  [2][4 * Hh];
__device__ float g_hbuf[2][Hh];
__device__ int   g_maskw[Tt * 4];
__device__ unsigned g_flag_h [NCTA * 64];
__device__ unsigned g_flag_cw[NCTA * 64];
__device__ int g_mask_kind;

// ---- mask dtype detection (u8/i32/f32) ----
__global__ void detect_kernel(const unsigned* __restrict__ wm) {
    __shared__ int f_gt1, f_f32;
    if (threadIdx.x == 0) { f_gt1 = 0; f_f32 = 0; }
    __syncthreads();
    for (int i = threadIdx.x; i < 4096; i += blockDim.x) {
        unsigned v = wm[i];
        if (v == 0x3F800000u) atomicOr(&f_f32, 1);
        else if (v > 1u)      atomicOr(&f_gt1, 1);
    }
    __syncthreads();
    if (threadIdx.x == 0) g_mask_kind = f_f32 ? 2 : (f_gt1 ? 0 : 1);
}

// ---- expand masks to int32 + zero barrier flags ----
__global__ void expand_masks(const void* __restrict__ wm) {
    int i = blockIdx.x * blockDim.x + threadIdx.x;   // 0..16383
    int mk = g_mask_kind;
    int m;
    if (mk == 0)      m = ((const unsigned char*)wm)[i] != 0;
    else if (mk == 2) m = ((const float*)wm)[i] != 0.f;
    else              m = ((const int*)wm)[i] != 0;
    g_maskw[i] = m;
    if (i < NCTA * 64) { g_flag_h[i] = 0u; g_flag_cw[i] = 0u; }
}

// ---- merged batched GEMM: 3 segments dispatched on blockIdx.x ----
#define BM 64
#define BN 64
#define BK 8
__global__ void gemm_all_kernel(const float* __restrict__ x, const int* __restrict__ wid,
                                const float* __restrict__ emb,
                                const float* __restrict__ W,  const float* __restrict__ b,
                                const float* __restrict__ Wa, const float* __restrict__ ba,
                                const float* __restrict__ Ww, const float* __restrict__ bw) {
    __shared__ float As[BK][BM];
    __shared__ float Bs[BK][BN];
    int bx = blockIdx.x;
    const float* A; const int* idx = nullptr;
    const float* B; const float* bias; float* C;
    int K, N, nx, rel;
    if (bx < 1536)      { rel = bx;        A = x;   B = W;  bias = b;  C = g_XW;   K = 128; N = 1536; nx = 24; }
    else if (bx < 2048) { rel = bx - 1536; A = x;   B = Wa; bias = ba; C = g_XWa;  K = 128; N = 512;  nx = 8;  }
    else                { rel = bx - 2048; A = emb; B = Ww; bias = bw; C = g_XwWw; K = 256; N = 1536; nx = 24; idx = wid; }
    const int bn0 = (rel % nx) * BN, bm0 = (rel / nx) * BM;
    const int tid = threadIdx.x;
    const int tx = tid & 15, ty = tid >> 4;
    const int lm = tid >> 2, lkk = (tid & 3) * 2;
    int arow = bm0 + lm;
    if (idx) arow = idx[arow];
    const float* aptr = A + (size_t)arow * K;
    const int bn = tid & 63, bkk = tid >> 6;

    float acc[4][4];
#pragma unroll
    for (int i = 0; i < 4; ++i)
#pragma unroll
        for (int j = 0; j < 4; ++j) acc[i][j] = 0.f;

    for (int k0 = 0; k0 < K; k0 += BK) {
        As[lkk][lm]     = aptr[k0 + lkk];
        As[lkk + 1][lm] = aptr[k0 + lkk + 1];
        Bs[bkk][bn]     = B[(size_t)(k0 + bkk) * N + bn0 + bn];
        Bs[bkk + 4][bn] = B[(size_t)(k0 + bkk + 4) * N + bn0 + bn];
        __syncthreads();
#pragma unroll
        for (int kk = 0; kk < BK; ++kk) {
            float4 av = *reinterpret_cast<const float4*>(&As[kk][ty * 4]);
            float4 bv = *reinterpret_cast<const float4*>(&Bs[kk][tx * 4]);
            float a[4] = {av.x, av.y, av.z, av.w};
            float b4[4] = {bv.x, bv.y, bv.z, bv.w};
#pragma unroll
            for (int i = 0; i < 4; ++i)
#pragma unroll
                for (int j = 0; j < 4; ++j) acc[i][j] += a[i] * b4[j];
        }
        __syncthreads();
    }
#pragma unroll
    for (int i = 0; i < 4; ++i) {
        size_t rbase = (size_t)(bm0 + ty * 4 + i) * N + bn0 + tx * 4;
#pragma unroll
        for (int j = 0; j < 4; ++j)
            C[rbase + j] = acc[i][j] + bias[bn0 + tx * 4 + j];
    }
}

// ---- contention-free flag barrier primitives ----
__device__ __forceinline__ void flag_post(unsigned* slot, unsigned epoch) {
    asm volatile("st.release.gpu.u32 [%0], %1;" :: "l"(slot), "r"(epoch) : "memory");
}
__device__ __forceinline__ void flag_wait(const unsigned* slot, unsigned epoch) {
    unsigned v;
    do {
        asm volatile("ld.acquire.gpu.u32 %0, [%1];" : "=r"(v) : "l"(slot) : "memory");
    } while (v < epoch);
}
__device__ __forceinline__ void cp16(uint32_t saddr, const void* g) {
    asm volatile("cp.async.cg.shared.global [%0], [%1], 16;" :: "r"(saddr), "l"(g) : "memory");
}
__device__ __forceinline__ void cp_commit() {
    asm volatile("cp.async.commit_group;" ::: "memory");
}
__device__ __forceinline__ void cp_wait0() {
    asm volatile("cp.async.wait_group 0;" ::: "memory");
}

struct __align__(16) CBuf {     // 544 B
    float xw[24];      // XW cols   (g*8 + jl)
    float xa[8];       // XWa cols
    float xww[96];     // XwWw cols (w*24 + g*8 + jl)
    int   mask[4];
    int   start[4];
};

__device__ __forceinline__ float sigf(float v) { return 1.f / (1.f + expf(-v)); }

#define SMEM_FLOATS 4096
#define SMEM_BYTES  (SMEM_FLOATS * 4)

__global__ void __launch_bounds__(NTH, 1)
lattice_seq_kernel(const float* __restrict__ h0, const float* __restrict__ c0,
                   const int* __restrict__ wstarts,
                   const float* __restrict__ U, const float* __restrict__ Ua,
                   const float* __restrict__ Uw, float* __restrict__ out) {
    extern __shared__ float sm[];
    float4* sh4    = (float4*)sm;            // h_prev  [512]f  (128 float4)
    float4* scw4   = (float4*)(sm + 512);    // c_w     [2048]f
    float*  sg     = sm + 2560;              // 24 gates (i|o|g per 8 jl)
    float*  salpha = sm + 2584;              // 32
    float*  rc     = sm + 2616;              // ring: own c slice [6][8]
    float*  rhuw   = sm + 2664;              // ring: own huw cols [6][24]
    CBuf*   cbuf   = (CBuf*)(sm + 2816);     // triple buffer

    const int tid = threadIdx.x;
    const int r   = blockIdx.x;              // owns H-cols r*8 .. r*8+7
    const int d   = tid >> 3,  l   = tid & 7;    // 48 dot groups x 8 lanes
    const int g16 = tid >> 4,  l16 = tid & 15;   // alpha groups x 16 lanes
    const int ajl = g16 & 7;

    // ========== init: weight column slices -> registers via SMEM staging ==========
    float wreg[64];   // U col (d<24) or Uw col (24<=d<48), elems i = m*32 + l*4 + k
    float ua[32];     // Ua col ajl, elems i = m*64 + l16*4 + k
    {
        auto stage8 = [&](const float* M, int colbase, int ldm) {
            for (int e = tid; e < 1024; e += NTH) {
                int i = e >> 1, c4 = e & 1;
                float4 v = *reinterpret_cast<const float4*>(&M[(size_t)i * ldm + colbase + c4 * 4]);
                sm[(c4 * 4 + 0) * 512 + i] = v.x; sm[(c4 * 4 + 1) * 512 + i] = v.y;
                sm[(c4 * 4 + 2) * 512 + i] = v.z; sm[(c4 * 4 + 3) * 512 + i] = v.w;
            }
        };
        for (int g = 0; g < 3; ++g) {
            stage8(U, g * 512 + r * 8, H3);
            __syncthreads();
            if (d < 24 && (d >> 3) == g) {
                int base = (d & 7) * 512 + l * 4;
#pragma unroll
                for (int m = 0; m < 16; ++m)
#pragma unroll
                    for (int k = 0; k < 4; ++k) wreg[m * 4 + k] = sm[base + m * 32 + k];
            }
            __syncthreads();
        }
        for (int g = 0; g < 3; ++g) {
            stage8(Uw, g * 512 + r * 8, H3);
            __syncthreads();
            if (d >= 24 && ((d - 24) >> 3) == g) {
                int base = ((d - 24) & 7) * 512 + l * 4;
#pragma unroll
                for (int m = 0; m < 16; ++m)
#pragma unroll
                    for (int k = 0; k < 4; ++k) wreg[m * 4 + k] = sm[base + m * 32 + k];
            }
            __syncthreads();
        }
        stage8(Ua, r * 8, Hh);
        __syncthreads();
        {
            int base = ajl * 512 + l16 * 4;
#pragma unroll
            for (int m = 0; m < 8; ++m)
#pragma unroll
                for (int k = 0; k < 4; ++k) ua[m * 4 + k] = sm[base + m * 64 + k];
        }
        __syncthreads();
    }

    // cp.async prefetch of step t1 constants into cbuf[t1%3] (threads 256..289, 34 ops)
    auto issue_prefetch = [&](int t1) {
        int e = tid - 256;
        if (e >= 0 && e < 34) {
            CBuf* nb2 = cbuf + (t1 % 3);
            const void* src;
            uint32_t dst;
            if (e < 24) {
                int w = e / 6, q = e % 6, g = q >> 1, c4 = q & 1;
                src = &g_XwWw[((size_t)(t1 * 4 + w)) * H3 + g * 512 + r * 8 + c4 * 4];
                dst = (uint32_t)__cvta_generic_to_shared(&nb2->xww[w * 24 + g * 8 + c4 * 4]);
            } else if (e < 30) {
                int f = e - 24, g = f >> 1, c4 = f & 1;
                src = &g_XW[(size_t)t1 * H3 + g * 512 + r * 8 + c4 * 4];
                dst = (uint32_t)__cvta_generic_to_shared(&nb2->xw[g * 8 + c4 * 4]);
            } else if (e < 32) {
                int q = e - 30;
                src = &g_XWa[(size_t)t1 * Hh + r * 8 + q * 4];
                dst = (uint32_t)__cvta_generic_to_shared(&nb2->xa[q * 4]);
            } else if (e == 32) {
                src = &wstarts[t1 * 4];
                dst = (uint32_t)__cvta_generic_to_shared(nb2->start);
            } else {
                src = &g_maskw[t1 * 4];
                dst = (uint32_t)__cvta_generic_to_shared(nb2->mask);
            }
            cp16(dst, src);
            cp_commit();
        }
    };

    issue_prefetch(0);
    issue_prefetch(1);
    if (tid >= 256 && tid < 290) cp_wait0();
    __syncthreads();

    unsigned lt = 0;   // late-step epoch (identical across CTAs)

    for (int t = 0; t < Tt; ++t) {
        CBuf* cb = cbuf + (t % 3);
        CBuf* nb = cbuf + ((t + 1) % 3);
        const int m0 = cb->mask[0], m1 = cb->mask[1], m2 = cb->mask[2], m3 = cb->mask[3];
        const int anyw = m0 | m1 | m2 | m3;
        const int haslate = (m0 & (cb->start[0] == t - 1)) | (m1 & (cb->start[1] == t - 1))
                          | (m2 & (cb->start[2] == t - 1)) | (m3 & (cb->start[3] == t - 1));
        if (haslate) ++lt;

        // ---- phase A: h poll+stage (0-127) | scw prestage (128-255) | cp drain (256-289) ----
        if (tid < 128) {
            if (t == 0) sh4[tid] = ((const float4*)h0)[tid];
            else {
                flag_wait(&g_flag_h[(tid >> 1) * 64], (unsigned)t);
                sh4[tid] = __ldcg((const float4*)g_hbuf[(t - 1) & 1] + tid);
            }
        } else if (tid < 256) {
            if (anyw && !haslate) {       // early-only step: data released by h flags
                int k = tid - 128;
                flag_wait(&g_flag_h[(k >> 1) * 64], (unsigned)t);
                const float4* src = (const float4*)g_cw[t & 1];
#pragma unroll
                for (int w = 0; w < 4; ++w)
                    scw4[(w << 7) + k] = __ldcg(src + (w << 7) + k);
            }
        } else if (tid < 290) {
            cp_wait0();
        }
        __syncthreads();   // S1

        // ---- phase B: 48 dots from registers (all 384 threads) ----
        {
            float a0 = 0.f, a1 = 0.f, a2 = 0.f, a3 = 0.f;
#pragma unroll
            for (int m = 0; m < 16; ++m) {
                float4 hv = sh4[m * 8 + l];
                a0 += wreg[m * 4 + 0] * hv.x;
                a1 += wreg[m * 4 + 1] * hv.y;
                a2 += wreg[m * 4 + 2] * hv.z;
                a3 += wreg[m * 4 + 3] * hv.w;
            }
            float acc = (a0 + a1) + (a2 + a3);
            acc += __shfl_down_sync(0xffffffffu, acc, 4, 8);
            acc += __shfl_down_sync(0xffffffffu, acc, 2, 8);
            acc += __shfl_down_sync(0xffffffffu, acc, 1, 8);
            if (l == 0) {
                if (d < 24) sg[d] = cb->xw[d] + acc;
                else if (t > 0) rhuw[((t - 1) % 6) * 24 + (d - 24)] = acc;
            }
        }
        __syncthreads();   // S2

        // ---- phase C: word cells, activations, prefetch, cw exchange ----
        if (tid < 32) {                     // late words of step t (single warp)
            if (haslate) {
                int w = tid >> 3, jl = tid & 7;
                if (cb->mask[w] && cb->start[w] == t - 1) {
                    int s = cb->start[w], slot = (s % 6) * 24;
                    float fv = cb->xww[w * 24 + 0 + jl] + rhuw[slot + 0 + jl];
                    float iv = cb->xww[w * 24 + 8 + jl] + rhuw[slot + 8 + jl];
                    float gv = cb->xww[w * 24 + 16 + jl] + rhuw[slot + 16 + jl];
                    float cs = rc[(s % 6) * 8 + jl];
                    g_cw[t & 1][(w << 9) + r * 8 + jl] = sigf(fv) * cs + sigf(iv) * tanhf(gv);
                }
                __syncwarp();
                if (tid == 0) flag_post(&g_flag_cw[r * 64], lt);
            }
        } else if (tid < 64) {              // early words of step t+1 (start <= t-1)
            if (t + 1 < Tt) {
                int idx = tid - 32, w = idx >> 3, jl = idx & 7;
                if (nb->mask[w] && nb->start[w] != t) {
                    int s = nb->start[w], slot = (s % 6) * 24;
                    float fv = nb->xww[w * 24 + 0 + jl] + rhuw[slot + 0 + jl];
                    float iv = nb->xww[w * 24 + 8 + jl] + rhuw[slot + 8 + jl];
                    float gv = nb->xww[w * 24 + 16 + jl] + rhuw[slot + 16 + jl];
                    float cs = rc[(s % 6) * 8 + jl];
                    g_cw[(t + 1) & 1][(w << 9) + r * 8 + jl] = sigf(fv) * cs + sigf(iv) * tanhf(gv);
                }
            }
        } else if (tid < 88) {              // gate activations
            int dd = tid - 64;
            float v = sg[dd];
            sg[dd] = (dd >= 16) ? tanhf(v) : sigf(v);
        } else if (tid >= 256 && tid < 290) {
            if (t + 2 < Tt) issue_prefetch(t + 2);
        }
        if (haslate && tid >= 128 && tid < 256) {   // pipelined c_w gather
            int k = tid - 128;
            flag_wait(&g_flag_cw[(k >> 1) * 64], lt);
            const float4* src = (const float4*)g_cw[t & 1];
#pragma unroll
            for (int w = 0; w < 4; ++w)
                scw4[(w << 7) + k] = __ldcg(src + (w << 7) + k);
        }
        __syncthreads();   // S3

        // ---- phase D: 32 alpha dots (c_w[w] @ Ua col), 16 lanes, 2 rounds ----
        if (anyw) {
            {   // round 1: groups 0..23 (w = 0..2)
                int w = g16 >> 3;
                float a0 = 0.f, a1 = 0.f, a2 = 0.f, a3 = 0.f;
                const float4* cc4 = scw4 + (w << 7);
#pragma unroll
                for (int m = 0; m < 8; ++m) {
                    float4 cv = cc4[m * 16 + l16];
                    a0 += ua[m * 4 + 0] * cv.x;
                    a1 += ua[m * 4 + 1] * cv.y;
                    a2 += ua[m * 4 + 2] * cv.z;
                    a3 += ua[m * 4 + 3] * cv.w;
                }
                float acc = (a0 + a1) + (a2 + a3);
                acc += __shfl_down_sync(0xffffffffu, acc, 8, 16);
                acc += __shfl_down_sync(0xffffffffu, acc, 4, 16);
                acc += __shfl_down_sync(0xffffffffu, acc, 2, 16);
                acc += __shfl_down_sync(0xffffffffu, acc, 1, 16);
                if (l16 == 0) salpha[g16] = sigf(cb->xa[ajl] + acc);
            }
            if (tid < 128) {   // round 2: w = 3 (same ajl per thread)
                float a0 = 0.f, a1 = 0.f, a2 = 0.f, a3 = 0.f;
                const float4* cc4 = scw4 + (3 << 7);
#pragma unroll
                for (int m = 0; m < 8; ++m) {
                    float4 cv = cc4[m * 16 + l16];
                    a0 += ua[m * 4 + 0] * cv.x;
                    a1 += ua[m * 4 + 1] * cv.y;
                    a2 += ua[m * 4 + 2] * cv.z;
                    a3 += ua[m * 4 + 3] * cv.w;
                }
                float acc = (a0 + a1) + (a2 + a3);
                acc += __shfl_down_sync(0xffffffffu, acc, 8, 16);
                acc += __shfl_down_sync(0xffffffffu, acc, 4, 16);
                acc += __shfl_down_sync(0xffffffffu, acc, 2, 16);
                acc += __shfl_down_sync(0xffffffffu, acc, 1, 16);
                if (l16 == 0) salpha[24 + g16] = sigf(cb->xa[ajl] + acc);
            }
            __syncthreads();   // S4
        }

        // ---- phase E: combine in warp 0; publish h slice + flag immediately ----
        if (tid < 32) {
            float h1 = 0.f, c1 = 0.f;
            if (tid < 8) {
                int jl = tid, j = r * 8 + jl;
                float ig = sg[jl], og = sg[8 + jl], gt = sg[16 + jl];
                if (anyw) {
                    float e0 = expf(ig);
                    float den = e0, num = e0 * gt;
#pragma unroll
                    for (int w = 0; w < 4; ++w)
                        if (cb->mask[w]) {
                            float ew = expf(salpha[w * 8 + jl]);
                            den += ew;
                            num += ew * ((const float*)scw4)[(w << 9) + j];
                        }
                    c1 = num / den;
                } else {
                    float cprev = (t == 0) ? c0[j] : rc[((t - 1) % 6) * 8 + jl];
                    c1 = (1.f - ig) * cprev + ig * gt;
                }
                h1 = og * tanhf(c1);
                rc[(t % 6) * 8 + jl] = c1;
            }
            int base4 = tid * 4;
            float y0 = __shfl_sync(0xffffffffu, h1, base4 + 0);
            float y1 = __shfl_sync(0xffffffffu, h1, base4 + 1);
            float y2 = __shfl_sync(0xffffffffu, h1, base4 + 2);
            float y3 = __shfl_sync(0xffffffffu, h1, base4 + 3);
            if (tid < 2) {
                float4 hv; hv.x = y0; hv.y = y1; hv.z = y2; hv.w = y3;
                ((float4*)g_hbuf[t & 1])[r * 2 + tid] = hv;
            }
            __syncwarp();
            if (tid == 0) flag_post(&g_flag_h[r * 64], (unsigned)(t + 1));
            if (tid < 8) {
                out[(size_t)t * 1024 + r * 8 + tid]       = h1;
                out[(size_t)t * 1024 + 512 + r * 8 + tid] = c1;
            }
        }
        __syncthreads();   // S5: protect scw4/sg/salpha reuse by next step's phase A/B
    }
}

extern "C" void kernel_launch(void* const* d_in, const int* in_sizes, int n_in,
                              void* d_out, int out_size) {
    const float* x   = (const float*)d_in[0];
    const int*   wid = (const int*)d_in[1];
    const int*   wst = (const int*)d_in[2];
    const void*  wm  = d_in[3];
    const float* h0  = (const float*)d_in[4];
    const float* c0  = (const float*)d_in[5];
    const float* emb = (const float*)d_in[6];
    const float* W   = (const float*)d_in[7];
    const float* U   = (const float*)d_in[8];
    const float* b   = (const float*)d_in[9];
    const float* Wa  = (const float*)d_in[10];
    const float* Ua  = (const float*)d_in[11];
    const float* ba  = (const float*)d_in[12];
    const float* Ww  = (const float*)d_in[13];
    const float* Uw  = (const float*)d_in[14];
    const float* bw  = (const float*)d_in[15];
    float* out = (float*)d_out;

    cudaFuncSetAttribute(lattice_seq_kernel,
                         cudaFuncAttributeMaxDynamicSharedMemorySize, SMEM_BYTES);

    detect_kernel<<<1, 256>>>((const unsigned*)wm);
    expand_masks<<<64, 256>>>(wm);
    gemm_all_kernel<<<8192, 256>>>(x, wid, emb, W, b, Wa, ba, Ww, bw);
    lattice_seq_kernel<<<NCTA, NTH, SMEM_BYTES>>>(h0, c0, wst, U, Ua, Uw, out);
}

// round 15
// speedup vs baseline: 2.4666x; 1.0799x over previous
#include <cuda_runtime.h>
#include <cstdint>

#define Tt   4096
#define Hh   512
#define H3   1536
#define NCTA 64
#define NTH  384
#define CANARY 0x7FA00BADu

__device__ float g_XW  [Tt * H3];
__device__ float g_XWa [Tt * Hh];
__device__ float g_XwWw[Tt * 4 * H3];
__device__ float g_cw  [2][4 * Hh];
__device__ float4 g_hmsg[3][256];          // chunk c at [c*2], 32B stride
__device__ int   g_maskw[Tt * 4];
__device__ unsigned g_flag_cw[NCTA * 64];
__device__ int g_mask_kind;

// ---- mask dtype detection (u8/i32/f32) ----
__global__ void detect_kernel(const unsigned* __restrict__ wm) {
    __shared__ int f_gt1, f_f32;
    if (threadIdx.x == 0) { f_gt1 = 0; f_f32 = 0; }
    __syncthreads();
    for (int i = threadIdx.x; i < 4096; i += blockDim.x) {
        unsigned v = wm[i];
        if (v == 0x3F800000u) atomicOr(&f_f32, 1);
        else if (v > 1u)      atomicOr(&f_gt1, 1);
    }
    __syncthreads();
    if (threadIdx.x == 0) g_mask_kind = f_f32 ? 2 : (f_gt1 ? 0 : 1);
}

// ---- expand masks + arm all h-message canaries + zero cw flags ----
__global__ void expand_masks(const void* __restrict__ wm) {
    int i = blockIdx.x * blockDim.x + threadIdx.x;   // 0..16383
    int mk = g_mask_kind;
    int m;
    if (mk == 0)      m = ((const unsigned char*)wm)[i] != 0;
    else if (mk == 2) m = ((const float*)wm)[i] != 0.f;
    else              m = ((const int*)wm)[i] != 0;
    g_maskw[i] = m;
    if (i < 3 * 256 * 4) ((unsigned*)g_hmsg)[i] = CANARY;
    if (i < NCTA * 64) g_flag_cw[i] = 0u;
}

// ---- merged batched GEMM: 3 segments dispatched on blockIdx.x ----
#define BM 64
#define BN 64
#define BK 8
__global__ void gemm_all_kernel(const float* __restrict__ x, const int* __restrict__ wid,
                                const float* __restrict__ emb,
                                const float* __restrict__ W,  const float* __restrict__ b,
                                const float* __restrict__ Wa, const float* __restrict__ ba,
                                const float* __restrict__ Ww, const float* __restrict__ bw) {
    __shared__ float As[BK][BM];
    __shared__ float Bs[BK][BN];
    int bx = blockIdx.x;
    const float* A; const int* idx = nullptr;
    const float* B; const float* bias; float* C;
    int K, N, nx, rel;
    if (bx < 1536)      { rel = bx;        A = x;   B = W;  bias = b;  C = g_XW;   K = 128; N = 1536; nx = 24; }
    else if (bx < 2048) { rel = bx - 1536; A = x;   B = Wa; bias = ba; C = g_XWa;  K = 128; N = 512;  nx = 8;  }
    else                { rel = bx - 2048; A = emb; B = Ww; bias = bw; C = g_XwWw; K = 256; N = 1536; nx = 24; idx = wid; }
    const int bn0 = (rel % nx) * BN, bm0 = (rel / nx) * BM;
    const int tid = threadIdx.x;
    const int tx = tid & 15, ty = tid >> 4;
    const int lm = tid >> 2, lkk = (tid & 3) * 2;
    int arow = bm0 + lm;
    if (idx) arow = idx[arow];
    const float* aptr = A + (size_t)arow * K;
    const int bn = tid & 63, bkk = tid >> 6;

    float acc[4][4];
#pragma unroll
    for (int i = 0; i < 4; ++i)
#pragma unroll
        for (int j = 0; j < 4; ++j) acc[i][j] = 0.f;

    for (int k0 = 0; k0 < K; k0 += BK) {
        As[lkk][lm]     = aptr[k0 + lkk];
        As[lkk + 1][lm] = aptr[k0 + lkk + 1];
        Bs[bkk][bn]     = B[(size_t)(k0 + bkk) * N + bn0 + bn];
        Bs[bkk + 4][bn] = B[(size_t)(k0 + bkk + 4) * N + bn0 + bn];
        __syncthreads();
#pragma unroll
        for (int kk = 0; kk < BK; ++kk) {
            float4 av = *reinterpret_cast<const float4*>(&As[kk][ty * 4]);
            float4 bv = *reinterpret_cast<const float4*>(&Bs[kk][tx * 4]);
            float a[4] = {av.x, av.y, av.z, av.w};
            float b4[4] = {bv.x, bv.y, bv.z, bv.w};
#pragma unroll
            for (int i = 0; i < 4; ++i)
#pragma unroll
                for (int j = 0; j < 4; ++j) acc[i][j] += a[i] * b4[j];
        }
        __syncthreads();
    }
#pragma unroll
    for (int i = 0; i < 4; ++i) {
        size_t rbase = (size_t)(bm0 + ty * 4 + i) * N + bn0 + tx * 4;
#pragma unroll
        for (int j = 0; j < 4; ++j)
            C[rbase + j] = acc[i][j] + bias[bn0 + tx * 4 + j];
    }
}

// ---- primitives ----
__device__ __forceinline__ void flag_post(unsigned* slot, unsigned epoch) {
    asm volatile("st.release.gpu.u32 [%0], %1;" :: "l"(slot), "r"(epoch) : "memory");
}
__device__ __forceinline__ void flag_wait(const unsigned* slot, unsigned epoch) {
    unsigned v;
    do {
        asm volatile("ld.acquire.gpu.u32 %0, [%1];" : "=r"(v) : "l"(slot) : "memory");
    } while (v < epoch);
}
__device__ __forceinline__ float4 ld_acq4(const float4* p) {
    float4 v;
    asm volatile("ld.acquire.gpu.global.v4.f32 {%0,%1,%2,%3}, [%4];"
                 : "=f"(v.x), "=f"(v.y), "=f"(v.z), "=f"(v.w) : "l"(p) : "memory");
    return v;
}
__device__ __forceinline__ void st_rel4(float4* p, float4 v) {
    asm volatile("st.release.gpu.global.v4.f32 [%0], {%1,%2,%3,%4};"
                 :: "l"(p), "f"(v.x), "f"(v.y), "f"(v.z), "f"(v.w) : "memory");
}
__device__ __forceinline__ void st_canary16(float4* p) {
    asm volatile("st.global.v4.u32 [%0], {%1,%1,%1,%1};" :: "l"(p), "r"(CANARY) : "memory");
}
__device__ __forceinline__ void cp16(uint32_t saddr, const void* g) {
    asm volatile("cp.async.cg.shared.global [%0], [%1], 16;" :: "r"(saddr), "l"(g) : "memory");
}
__device__ __forceinline__ void cp_commit() {
    asm volatile("cp.async.commit_group;" ::: "memory");
}
__device__ __forceinline__ void cp_wait0() {
    asm volatile("cp.async.wait_group 0;" ::: "memory");
}

struct __align__(16) CBuf {     // 544 B
    float xw[24];      // XW cols   (g*8 + jl)
    float xa[8];       // XWa cols
    float xww[96];     // XwWw cols (w*24 + g*8 + jl)
    int   mask[4];
    int   start[4];
};

__device__ __forceinline__ float sigf(float v) { return 1.f / (1.f + expf(-v)); }

#define SMEM_FLOATS 4096
#define SMEM_BYTES  (SMEM_FLOATS * 4)

__global__ void __launch_bounds__(NTH, 1)
lattice_seq_kernel(const float* __restrict__ h0, const float* __restrict__ c0,
                   const int* __restrict__ wstarts,
                   const float* __restrict__ U, const float* __restrict__ Ua,
                   const float* __restrict__ Uw, float* __restrict__ out) {
    extern __shared__ float sm[];
    float4* sh4    = (float4*)sm;            // h_prev  [512]f  (128 float4)
    float4* scw4   = (float4*)(sm + 512);    // c_w     [2048]f
    float*  sg     = sm + 2560;              // 24 gates (i|o|g per 8 jl)
    float*  salpha = sm + 2584;              // 32
    float*  rc     = sm + 2616;              // ring: own c slice [6][8]
    float*  rhuw   = sm + 2664;              // ring: own huw cols [6][24]
    CBuf*   cbuf   = (CBuf*)(sm + 2816);     // triple buffer

    const int tid = threadIdx.x;
    const int r   = blockIdx.x;              // owns H-cols r*8 .. r*8+7
    const int d   = tid >> 3,  l   = tid & 7;    // 48 dot groups x 8 lanes
    const int g16 = tid >> 4,  l16 = tid & 15;   // alpha groups x 16 lanes
    const int ajl = g16 & 7;

    // ========== init: weight column slices -> registers via SMEM staging ==========
    float wreg[64];   // U col (d<24) or Uw col (24<=d<48), elems i = m*32 + l*4 + k
    float ua[32];     // Ua col ajl, elems i = m*64 + l16*4 + k
    {
        auto stage8 = [&](const float* M, int colbase, int ldm) {
            for (int e = tid; e < 1024; e += NTH) {
                int i = e >> 1, c4 = e & 1;
                float4 v = *reinterpret_cast<const float4*>(&M[(size_t)i * ldm + colbase + c4 * 4]);
                sm[(c4 * 4 + 0) * 512 + i] = v.x; sm[(c4 * 4 + 1) * 512 + i] = v.y;
                sm[(c4 * 4 + 2) * 512 + i] = v.z; sm[(c4 * 4 + 3) * 512 + i] = v.w;
            }
        };
        for (int g = 0; g < 3; ++g) {
            stage8(U, g * 512 + r * 8, H3);
            __syncthreads();
            if (d < 24 && (d >> 3) == g) {
                int base = (d & 7) * 512 + l * 4;
#pragma unroll
                for (int m = 0; m < 16; ++m)
#pragma unroll
                    for (int k = 0; k < 4; ++k) wreg[m * 4 + k] = sm[base + m * 32 + k];
            }
            __syncthreads();
        }
        for (int g = 0; g < 3; ++g) {
            stage8(Uw, g * 512 + r * 8, H3);
            __syncthreads();
            if (d >= 24 && ((d - 24) >> 3) == g) {
                int base = ((d - 24) & 7) * 512 + l * 4;
#pragma unroll
                for (int m = 0; m < 16; ++m)
#pragma unroll
                    for (int k = 0; k < 4; ++k) wreg[m * 4 + k] = sm[base + m * 32 + k];
            }
            __syncthreads();
        }
        stage8(Ua, r * 8, Hh);
        __syncthreads();
        {
            int base = ajl * 512 + l16 * 4;
#pragma unroll
            for (int m = 0; m < 8; ++m)
#pragma unroll
                for (int k = 0; k < 4; ++k) ua[m * 4 + k] = sm[base + m * 64 + k];
        }
        __syncthreads();
    }

    // cp.async prefetch of step t1 constants into cbuf[t1%3] (threads 256..289, 34 ops)
    auto issue_prefetch = [&](int t1) {
        int e = tid - 256;
        if (e >= 0 && e < 34) {
            CBuf* nb2 = cbuf + (t1 % 3);
            const void* src;
            uint32_t dst;
            if (e < 24) {
                int w = e / 6, q = e % 6, g = q >> 1, c4 = q & 1;
                src = &g_XwWw[((size_t)(t1 * 4 + w)) * H3 + g * 512 + r * 8 + c4 * 4];
                dst = (uint32_t)__cvta_generic_to_shared(&nb2->xww[w * 24 + g * 8 + c4 * 4]);
            } else if (e < 30) {
                int f = e - 24, g = f >> 1, c4 = f & 1;
                src = &g_XW[(size_t)t1 * H3 + g * 512 + r * 8 + c4 * 4];
                dst = (uint32_t)__cvta_generic_to_shared(&nb2->xw[g * 8 + c4 * 4]);
            } else if (e < 32) {
                int q = e - 30;
                src = &g_XWa[(size_t)t1 * Hh + r * 8 + q * 4];
                dst = (uint32_t)__cvta_generic_to_shared(&nb2->xa[q * 4]);
            } else if (e == 32) {
                src = &wstarts[t1 * 4];
                dst = (uint32_t)__cvta_generic_to_shared(nb2->start);
            } else {
                src = &g_maskw[t1 * 4];
                dst = (uint32_t)__cvta_generic_to_shared(nb2->mask);
            }
            cp16(dst, src);
            cp_commit();
        }
    };

    issue_prefetch(0);
    issue_prefetch(1);
    if (tid >= 256 && tid < 290) cp_wait0();
    __syncthreads();

    unsigned lt = 0;   // late-step epoch (identical across CTAs)

    for (int t = 0; t < Tt; ++t) {
        CBuf* cb = cbuf + (t % 3);
        CBuf* nb = cbuf + ((t + 1) % 3);
        const int m0 = cb->mask[0], m1 = cb->mask[1], m2 = cb->mask[2], m3 = cb->mask[3];
        const int anyw = m0 | m1 | m2 | m3;
        const int haslate = (m0 & (cb->start[0] == t - 1)) | (m1 & (cb->start[1] == t - 1))
                          | (m2 & (cb->start[2] == t - 1)) | (m3 & (cb->start[3] == t - 1));
        if (haslate) ++lt;

        // ---- phase A: tagged-message h poll (0-127) | scw prestage (128-255) | cp drain ----
        if (tid < 128) {
            if (t == 0) sh4[tid] = ((const float4*)h0)[tid];
            else {
                const float4* p = &g_hmsg[(t - 1) % 3][tid * 2];
                float4 v;
                do { v = ld_acq4(p); } while (__float_as_uint(v.x) == CANARY);
                sh4[tid] = v;    // payload IS h[4*tid .. 4*tid+3]
            }
        } else if (tid < 256) {
            if (anyw && !haslate) {       // early-only step: order via owner's h message
                int k = tid - 128;
                const float4* p = &g_hmsg[(t - 1) % 3][k * 2];
                float4 v;
                do { v = ld_acq4(p); } while (__float_as_uint(v.x) == CANARY);
                const float4* src = (const float4*)g_cw[t & 1];
#pragma unroll
                for (int w = 0; w < 4; ++w)
                    scw4[(w << 7) + k] = __ldcg(src + (w << 7) + k);
            }
        } else if (tid < 290) {
            cp_wait0();
        }
        __syncthreads();   // S1

        // ---- phase B: 48 dots from registers (all 384 threads) ----
        {
            float a0 = 0.f, a1 = 0.f, a2 = 0.f, a3 = 0.f;
#pragma unroll
            for (int m = 0; m < 16; ++m) {
                float4 hv = sh4[m * 8 + l];
                a0 += wreg[m * 4 + 0] * hv.x;
                a1 += wreg[m * 4 + 1] * hv.y;
                a2 += wreg[m * 4 + 2] * hv.z;
                a3 += wreg[m * 4 + 3] * hv.w;
            }
            float acc = (a0 + a1) + (a2 + a3);
            acc += __shfl_down_sync(0xffffffffu, acc, 4, 8);
            acc += __shfl_down_sync(0xffffffffu, acc, 2, 8);
            acc += __shfl_down_sync(0xffffffffu, acc, 1, 8);
            if (l == 0) {
                if (d < 24) sg[d] = cb->xw[d] + acc;
                else if (t > 0) rhuw[((t - 1) % 6) * 24 + (d - 24)] = acc;
            }
        }
        __syncthreads();   // S2

        // ---- phase C: word cells, activations, canary arm, prefetch, cw exchange ----
        if (tid < 32) {                     // late words of step t (single warp)
            if (haslate) {
                int w = tid >> 3, jl = tid & 7;
                if (cb->mask[w] && cb->start[w] == t - 1) {
                    int s = cb->start[w], slot = (s % 6) * 24;
                    float fv = cb->xww[w * 24 + 0 + jl] + rhuw[slot + 0 + jl];
                    float iv = cb->xww[w * 24 + 8 + jl] + rhuw[slot + 8 + jl];
                    float gv = cb->xww[w * 24 + 16 + jl] + rhuw[slot + 16 + jl];
                    float cs = rc[(s % 6) * 8 + jl];
                    g_cw[t & 1][(w << 9) + r * 8 + jl] = sigf(fv) * cs + sigf(iv) * tanhf(gv);
                }
                __syncwarp();
                if (tid == 0) flag_post(&g_flag_cw[r * 64], lt);
            }
        } else if (tid < 64) {              // early words of step t+1 (start <= t-1)
            if (t + 1 < Tt) {
                int idx = tid - 32, w = idx >> 3, jl = idx & 7;
                if (nb->mask[w] && nb->start[w] != t) {
                    int s = nb->start[w], slot = (s % 6) * 24;
                    float fv = nb->xww[w * 24 + 0 + jl] + rhuw[slot + 0 + jl];
                    float iv = nb->xww[w * 24 + 8 + jl] + rhuw[slot + 8 + jl];
                    float gv = nb->xww[w * 24 + 16 + jl] + rhuw[slot + 16 + jl];
                    float cs = rc[(s % 6) * 8 + jl];
                    g_cw[(t + 1) & 1][(w << 9) + r * 8 + jl] = sigf(fv) * cs + sigf(iv) * tanhf(gv);
                }
            }
        } else if (tid < 88) {              // gate activations
            int dd = tid - 64;
            float v = sg[dd];
            sg[dd] = (dd >= 16) ? tanhf(v) : sigf(v);
        } else if (tid < 90) {              // arm canaries of the buffer carrying h[t+1]
            st_canary16(&g_hmsg[(t + 1) % 3][(r * 2 + (tid - 88)) * 2]);
        } else if (tid >= 256 && tid < 290) {
            if (t + 2 < Tt) issue_prefetch(t + 2);
        }
        if (haslate && tid >= 128 && tid < 256) {   // pipelined c_w gather
            int k = tid - 128;
            flag_wait(&g_flag_cw[(k >> 1) * 64], lt);
            const float4* src = (const float4*)g_cw[t & 1];
#pragma unroll
            for (int w = 0; w < 4; ++w)
                scw4[(w << 7) + k] = __ldcg(src + (w << 7) + k);
        }
        __syncthreads();   // S3

        // ---- phase D: 32 alpha dots (c_w[w] @ Ua col), 16 lanes, 2 rounds ----
        if (anyw) {
            {   // round 1: groups 0..23 (w = 0..2)
                int w = g16 >> 3;
                float a0 = 0.f, a1 = 0.f, a2 = 0.f, a3 = 0.f;
                const float4* cc4 = scw4 + (w << 7);
#pragma unroll
                for (int m = 0; m < 8; ++m) {
                    float4 cv = cc4[m * 16 + l16];
                    a0 += ua[m * 4 + 0] * cv.x;
                    a1 += ua[m * 4 + 1] * cv.y;
                    a2 += ua[m * 4 + 2] * cv.z;
                    a3 += ua[m * 4 + 3] * cv.w;
                }
                float acc = (a0 + a1) + (a2 + a3);
                acc += __shfl_down_sync(0xffffffffu, acc, 8, 16);
                acc += __shfl_down_sync(0xffffffffu, acc, 4, 16);
                acc += __shfl_down_sync(0xffffffffu, acc, 2, 16);
                acc += __shfl_down_sync(0xffffffffu, acc, 1, 16);
                if (l16 == 0) salpha[g16] = sigf(cb->xa[ajl] + acc);
            }
            if (tid < 128) {   // round 2: w = 3 (same ajl per thread)
                float a0 = 0.f, a1 = 0.f, a2 = 0.f, a3 = 0.f;
                const float4* cc4 = scw4 + (3 << 7);
#pragma unroll
                for (int m = 0; m < 8; ++m) {
                    float4 cv = cc4[m * 16 + l16];
                    a0 += ua[m * 4 + 0] * cv.x;
                    a1 += ua[m * 4 + 1] * cv.y;
                    a2 += ua[m * 4 + 2] * cv.z;
                    a3 += ua[m * 4 + 3] * cv.w;
                }
                float acc = (a0 + a1) + (a2 + a3);
                acc += __shfl_down_sync(0xffffffffu, acc, 8, 16);
                acc += __shfl_down_sync(0xffffffffu, acc, 4, 16);
                acc += __shfl_down_sync(0xffffffffu, acc, 2, 16);
                acc += __shfl_down_sync(0xffffffffu, acc, 1, 16);
                if (l16 == 0) salpha[24 + g16] = sigf(cb->xa[ajl] + acc);
            }
            __syncthreads();   // S4
        }

        // ---- phase E: combine in warp 0; publish tagged h message immediately ----
        if (tid < 32) {
            float h1 = 0.f, c1 = 0.f;
            if (tid < 8) {
                int jl = tid, j = r * 8 + jl;
                float ig = sg[jl], og = sg[8 + jl], gt = sg[16 + jl];
                if (anyw) {
                    float e0 = expf(ig);
                    float den = e0, num = e0 * gt;
#pragma unroll
                    for (int w = 0; w < 4; ++w)
                        if (cb->mask[w]) {
                            float ew = expf(salpha[w * 8 + jl]);
                            den += ew;
                            num += ew * ((const float*)scw4)[(w << 9) + j];
                        }
                    c1 = num / den;
                } else {
                    float cprev = (t == 0) ? c0[j] : rc[((t - 1) % 6) * 8 + jl];
                    c1 = (1.f - ig) * cprev + ig * gt;
                }
                h1 = og * tanhf(c1);
                rc[(t % 6) * 8 + jl] = c1;
            }
            int base4 = tid * 4;
            float y0 = __shfl_sync(0xffffffffu, h1, base4 + 0);
            float y1 = __shfl_sync(0xffffffffu, h1, base4 + 1);
            float y2 = __shfl_sync(0xffffffffu, h1, base4 + 2);
            float y3 = __shfl_sync(0xffffffffu, h1, base4 + 3);
            if (tid < 2) {
                float4 hv; hv.x = y0; hv.y = y1; hv.z = y2; hv.w = y3;
                st_rel4(&g_hmsg[t % 3][(r * 2 + tid) * 2], hv);   // data IS the flag
            }
            if (tid < 8) {
                out[(size_t)t * 1024 + r * 8 + tid]       = h1;
                out[(size_t)t * 1024 + 512 + r * 8 + tid] = c1;
            }
        }
        __syncthreads();   // S5: protect scw4/sg/salpha reuse; orders arm before next post
    }
}

extern "C" void kernel_launch(void* const* d_in, const int* in_sizes, int n_in,
                              void* d_out, int out_size) {
    const float* x   = (const float*)d_in[0];
    const int*   wid = (const int*)d_in[1];
    const int*   wst = (const int*)d_in[2];
    const void*  wm  = d_in[3];
    const float* h0  = (const float*)d_in[4];
    const float* c0  = (const float*)d_in[5];
    const float* emb = (const float*)d_in[6];
    const float* W   = (const float*)d_in[7];
    const float* U   = (const float*)d_in[8];
    const float* b   = (const float*)d_in[9];
    const float* Wa  = (const float*)d_in[10];
    const float* Ua  = (const float*)d_in[11];
    const float* ba  = (const float*)d_in[12];
    const float* Ww  = (const float*)d_in[13];
    const float* Uw  = (const float*)d_in[14];
    const float* bw  = (const float*)d_in[15];
    float* out = (float*)d_out;

    cudaFuncSetAttribute(lattice_seq_kernel,
                         cudaFuncAttributeMaxDynamicSharedMemorySize, SMEM_BYTES);

    detect_kernel<<<1, 256>>>((const unsigned*)wm);
    expand_masks<<<64, 256>>>(wm);
    gemm_all_kernel<<<8192, 256>>>(x, wid, emb, W, b, Wa, ba, Ww, bw);
    lattice_seq_kernel<<<NCTA, NTH, SMEM_BYTES>>>(h0, c0, wst, U, Ua, Uw, out);
}